// round 14
// baseline (speedup 1.0000x reference)
#include <cuda_runtime.h>
#include <cstdint>

// DeepMapping2D occupancy_generation, GB300 sm_103a.  Round 14 — FREEZE.
// Byte-equivalent revert to the R12 session-best (115.3us).
//
//   output[b] = K_b ones then zeros, K_b = #bins with count >= 53
//   (count/262144 > 2e-4). The per-cloud min-shift is a bijection on bins
//   (z stays in [0,1024) either way) -> K_b is shift-invariant -> no min
//   pass, no top-k, no second scan.
//
// Final validated model (R1-R13):
//   * hist: 16.7M u8 REDG RMWs -> ~1.2GB of L2 sector traffic, pinned at
//     the LTS cap (~95us). Falsified alternatives: issue-dieting (R2/R4),
//     extra per-thread MLP (R5: occ drop), ATOMG returns (R6: +44us),
//     stream forks (R9: +16us), grid-wide fences (R3: +110us),
//     smem/DSMEM privatization (priced out on ATOMS issue floors).
//   * count: read-only uint4 scan, grid (64,64), ~9us (R13's deeper-MLP
//     variant regressed).
//   * re-zero: cudaMemsetAsync, driver write path, ~5us (beats any store
//     kernel tried).
//   * out: distributed float4 writes, ~2us; g_count reset rides the next
//     replay's hist kernel (kernel boundaries provide all ordering; the
//     state invariant is identical on every call, so correctness run,
//     capture, and replays all see the same behavior).

#define NBATCH  64
#define NPTS    262144
#define TOPK    5120
#define GZ_LOG2 10
#define BINS_PER_BATCH   (1024u * 1024u)          // 1M u8 bins / batch
#define HWORDS_PER_BATCH (BINS_PER_BATCH / 4)     // 256K u32 / batch

__device__ unsigned int g_hist[(size_t)NBATCH * HWORDS_PER_BATCH];  // 64 MB, load-zeroed
__device__ unsigned int g_count[NBATCH];                            // load-zeroed

// ---------------------------------------------------------------------------
// Kernel 1: histogram scatter, RED-only byte adds + per-batch counter reset.
// grid (64, 64) x 256 thr; grid-stride, unroll 4. Measured 94-96us (floor).
// ---------------------------------------------------------------------------
__global__ void dm2d_hist_kernel(const float4* __restrict__ pcd) {
    const int b = blockIdx.y;
    if (blockIdx.x == 0 && threadIdx.x == 0)
        g_count[b] = 0u;                           // reset (prev replay's value)

    unsigned int* __restrict__ hist = g_hist + (size_t)b * HWORDS_PER_BATCH;
    const float4* __restrict__ base = pcd + (size_t)b * (NPTS / 2);

    const int tid    = blockIdx.x * blockDim.x + threadIdx.x;
    const int stride = gridDim.x * blockDim.x;

    #pragma unroll 4
    for (int i = tid; i < NPTS / 2; i += stride) {
        float4 p = __ldcs(&base[i]);   // two points: (x0,z0,x1,z1); evict-first

        // jnp.round = round-half-to-even == rintf under default RN mode.
        unsigned x0 = (unsigned)(int)rintf(1000.0f * p.x);
        unsigned z0 = (unsigned)(int)rintf(1000.0f * p.y);
        unsigned x1 = (unsigned)(int)rintf(1000.0f * p.z);
        unsigned z1 = (unsigned)(int)rintf(1000.0f * p.w);

        unsigned i0 = (x0 << GZ_LOG2) | z0;
        unsigned i1 = (x1 << GZ_LOG2) | z1;

        // fire-and-forget byte increments (return unused -> REDG)
        atomicAdd(&hist[i0 >> 2], 1u << ((i0 & 3u) << 3));
        atomicAdd(&hist[i1 >> 2], 1u << ((i1 & 3u) << 3));
    }
}

// ---------------------------------------------------------------------------
// Kernel 2: count bins >= 53 per batch. READ-ONLY over the L2-resident hist.
// grid (64, 64) x 256 thr; 4 uint4 = 64 bins per thread. Measured ~9us.
// ---------------------------------------------------------------------------
__global__ void dm2d_count_kernel() {
    const int b = blockIdx.y;
    const uint4* __restrict__ hist4 =
        reinterpret_cast<const uint4*>(g_hist + (size_t)b * HWORDS_PER_BATCH);

    const int tid = blockIdx.x * 256 + threadIdx.x;   // 0..16383

    unsigned int cnt = 0;
    #pragma unroll
    for (int u = 0; u < 4; u++) {
        uint4 w = hist4[tid + u * 16384];
        cnt += __popc(__vcmpgeu4(w.x, 0x35353535u) & 0x01010101u);
        cnt += __popc(__vcmpgeu4(w.y, 0x35353535u) & 0x01010101u);
        cnt += __popc(__vcmpgeu4(w.z, 0x35353535u) & 0x01010101u);
        cnt += __popc(__vcmpgeu4(w.w, 0x35353535u) & 0x01010101u);
    }

    #pragma unroll
    for (int off = 16; off > 0; off >>= 1)
        cnt += __shfl_down_sync(0xFFFFFFFFu, cnt, off);
    if ((threadIdx.x & 31) == 0 && cnt)
        atomicAdd(&g_count[b], cnt);
}

// ---------------------------------------------------------------------------
// Kernel 3: output expansion, distributed float4 writes.
// grid (5, 64) x 256 thr: 1280 float4 = 5120 floats per batch.
// ---------------------------------------------------------------------------
__global__ void dm2d_out_kernel(float* __restrict__ out) {
    const int b = blockIdx.y;
    const int tid = blockIdx.x * 256 + threadIdx.x;   // 0..1279
    const int K = (int)g_count[b];
    const int i = tid * 4;
    float4 v;
    v.x = (i + 0 < K) ? 1.0f : 0.0f;
    v.y = (i + 1 < K) ? 1.0f : 0.0f;
    v.z = (i + 2 < K) ? 1.0f : 0.0f;
    v.w = (i + 3 < K) ? 1.0f : 0.0f;
    reinterpret_cast<float4*>(out + (size_t)b * TOPK)[tid] = v;
}

extern "C" void kernel_launch(void* const* d_in, const int* in_sizes, int n_in,
                              void* d_out, int out_size) {
    (void)in_sizes; (void)n_in; (void)out_size;
    const float4* pcd = reinterpret_cast<const float4*>(d_in[0]);
    float* out = reinterpret_cast<float*>(d_out);

    dm2d_hist_kernel<<<dim3(64, NBATCH), 256>>>(pcd);
    dm2d_count_kernel<<<dim3(64, NBATCH), 256>>>();

    // Re-zero the histogram for the next replay (driver-tuned write path),
    // then expand the output. R12-exact launch order.
    void* hist_ptr = nullptr;
    cudaGetSymbolAddress(&hist_ptr, g_hist);
    cudaMemsetAsync(hist_ptr, 0, (size_t)NBATCH * BINS_PER_BATCH, 0);
    dm2d_out_kernel<<<dim3(5, NBATCH), 256>>>(out);
}

// round 15
// speedup vs baseline: 1.0133x; 1.0133x over previous
#include <cuda_runtime.h>
#include <cstdint>

// DeepMapping2D occupancy_generation, GB300 sm_103a.  Round 15.
// R12 session-best structure + one refinement: the final re-zero (memset)
// and the output expansion are INDEPENDENT (memset: g_hist; out: g_count ->
// d_out), so they run as parallel graph branches instead of a chain.
//
//   output[b] = K_b ones then zeros, K_b = #bins with count >= 53.
//   Min-shift is a bin bijection -> K_b shift-invariant -> no min pass.
//
// Final model (R1-R14): hist pinned at the LTS sector-RMW floor
// (16.7M RMWs / 184 LTS x 2cyc ~= 96us; measured 94.2-95.9 across every
// variant). count ~9us, memset ~5us, out ~2us. R14 proved a +-2us
// run-to-run noise band in the aux region.

#define NBATCH  64
#define NPTS    262144
#define TOPK    5120
#define GZ_LOG2 10
#define BINS_PER_BATCH   (1024u * 1024u)          // 1M u8 bins / batch
#define HWORDS_PER_BATCH (BINS_PER_BATCH / 4)     // 256K u32 / batch

__device__ unsigned int g_hist[(size_t)NBATCH * HWORDS_PER_BATCH];  // 64 MB, load-zeroed
__device__ unsigned int g_count[NBATCH];                            // load-zeroed

// ---------------------------------------------------------------------------
// Kernel 1: histogram scatter, RED-only byte adds + per-batch counter reset.
// grid (64, 64) x 256 thr; grid-stride, unroll 4. Measured 94-96us (floor).
// ---------------------------------------------------------------------------
__global__ void dm2d_hist_kernel(const float4* __restrict__ pcd) {
    const int b = blockIdx.y;
    if (blockIdx.x == 0 && threadIdx.x == 0)
        g_count[b] = 0u;                           // reset (prev replay's value)

    unsigned int* __restrict__ hist = g_hist + (size_t)b * HWORDS_PER_BATCH;
    const float4* __restrict__ base = pcd + (size_t)b * (NPTS / 2);

    const int tid    = blockIdx.x * blockDim.x + threadIdx.x;
    const int stride = gridDim.x * blockDim.x;

    #pragma unroll 4
    for (int i = tid; i < NPTS / 2; i += stride) {
        float4 p = __ldcs(&base[i]);   // two points: (x0,z0,x1,z1); evict-first

        // jnp.round = round-half-to-even == rintf under default RN mode.
        unsigned x0 = (unsigned)(int)rintf(1000.0f * p.x);
        unsigned z0 = (unsigned)(int)rintf(1000.0f * p.y);
        unsigned x1 = (unsigned)(int)rintf(1000.0f * p.z);
        unsigned z1 = (unsigned)(int)rintf(1000.0f * p.w);

        unsigned i0 = (x0 << GZ_LOG2) | z0;
        unsigned i1 = (x1 << GZ_LOG2) | z1;

        // fire-and-forget byte increments (return unused -> REDG)
        atomicAdd(&hist[i0 >> 2], 1u << ((i0 & 3u) << 3));
        atomicAdd(&hist[i1 >> 2], 1u << ((i1 & 3u) << 3));
    }
}

// ---------------------------------------------------------------------------
// Kernel 2: count bins >= 53 per batch. READ-ONLY over the L2-resident hist.
// grid (64, 64) x 256 thr; 4 uint4 = 64 bins per thread. Measured ~9us.
// ---------------------------------------------------------------------------
__global__ void dm2d_count_kernel() {
    const int b = blockIdx.y;
    const uint4* __restrict__ hist4 =
        reinterpret_cast<const uint4*>(g_hist + (size_t)b * HWORDS_PER_BATCH);

    const int tid = blockIdx.x * 256 + threadIdx.x;   // 0..16383

    unsigned int cnt = 0;
    #pragma unroll
    for (int u = 0; u < 4; u++) {
        uint4 w = hist4[tid + u * 16384];
        cnt += __popc(__vcmpgeu4(w.x, 0x35353535u) & 0x01010101u);
        cnt += __popc(__vcmpgeu4(w.y, 0x35353535u) & 0x01010101u);
        cnt += __popc(__vcmpgeu4(w.z, 0x35353535u) & 0x01010101u);
        cnt += __popc(__vcmpgeu4(w.w, 0x35353535u) & 0x01010101u);
    }

    #pragma unroll
    for (int off = 16; off > 0; off >>= 1)
        cnt += __shfl_down_sync(0xFFFFFFFFu, cnt, off);
    if ((threadIdx.x & 31) == 0 && cnt)
        atomicAdd(&g_count[b], cnt);
}

// ---------------------------------------------------------------------------
// Kernel 3: output expansion, distributed float4 writes.
// grid (5, 64) x 256 thr: 1280 float4 = 5120 floats per batch.
// ---------------------------------------------------------------------------
__global__ void dm2d_out_kernel(float* __restrict__ out) {
    const int b = blockIdx.y;
    const int tid = blockIdx.x * 256 + threadIdx.x;   // 0..1279
    const int K = (int)g_count[b];
    const int i = tid * 4;
    float4 v;
    v.x = (i + 0 < K) ? 1.0f : 0.0f;
    v.y = (i + 1 < K) ? 1.0f : 0.0f;
    v.z = (i + 2 < K) ? 1.0f : 0.0f;
    v.w = (i + 3 < K) ? 1.0f : 0.0f;
    reinterpret_cast<float4*>(out + (size_t)b * TOPK)[tid] = v;
}

extern "C" void kernel_launch(void* const* d_in, const int* in_sizes, int n_in,
                              void* d_out, int out_size) {
    (void)in_sizes; (void)n_in; (void)out_size;
    const float4* pcd = reinterpret_cast<const float4*>(d_in[0]);
    float* out = reinterpret_cast<float*>(d_out);

    void* hist_ptr = nullptr;
    cudaGetSymbolAddress(&hist_ptr, g_hist);

    dm2d_hist_kernel<<<dim3(64, NBATCH), 256>>>(pcd);
    dm2d_count_kernel<<<dim3(64, NBATCH), 256>>>();

    // memset (re-zero for next replay) and out are independent: run them as
    // parallel graph branches. Fallback = exact R12 sequential order.
    cudaStream_t s1 = nullptr;
    cudaEvent_t eFork = nullptr, eJoin = nullptr;
    bool forked =
        cudaStreamCreateWithFlags(&s1, cudaStreamNonBlocking) == cudaSuccess &&
        cudaEventCreateWithFlags(&eFork, cudaEventDisableTiming) == cudaSuccess &&
        cudaEventCreateWithFlags(&eJoin, cudaEventDisableTiming) == cudaSuccess;

    if (forked) {
        cudaEventRecord(eFork, 0);
        cudaStreamWaitEvent(s1, eFork, 0);
        cudaMemsetAsync(hist_ptr, 0, (size_t)NBATCH * BINS_PER_BATCH, s1); // branch A
        cudaEventRecord(eJoin, s1);
        dm2d_out_kernel<<<dim3(5, NBATCH), 256>>>(out);                    // branch B
        cudaStreamWaitEvent(0, eJoin, 0);                                  // join
    } else {
        cudaMemsetAsync(hist_ptr, 0, (size_t)NBATCH * BINS_PER_BATCH, 0);
        dm2d_out_kernel<<<dim3(5, NBATCH), 256>>>(out);
    }
}